// round 5
// baseline (speedup 1.0000x reference)
#include <cuda_runtime.h>
#include <cstdint>

#define PP    8       // personas
#define FF    64      // factor dim
#define SB    200     // items per batch row
#define RPB   4       // batches per CTA
#define TPB   224
#define NCOMP 200     // compute threads (50 per batch)
#define RR    4       // rows per compute thread (same batch)
#define VPITCH 272    // bytes per v row in smem: 17 x 16B (odd -> conflict-free LDS.128)
#define U_SZ  (PP * FF * 4)          // 2048 B per user
#define U_OFF (RPB * SB * VPITCH)    // 217600
#define SMEMB (U_OFF + RPB * U_SZ)   // 225792 B dynamic smem

typedef unsigned long long ull;

__device__ __forceinline__ ull fma2(ull a, ull b, ull c) {
    ull d; asm("fma.rn.f32x2 %0, %1, %2, %3;" : "=l"(d) : "l"(a), "l"(b), "l"(c)); return d;
}
__device__ __forceinline__ void lds16(ull& a, ull& b, uint32_t addr) {
    asm volatile("ld.shared.v2.b64 {%0,%1}, [%2];" : "=l"(a), "=l"(b) : "r"(addr));
}
__device__ __forceinline__ float hsum2(ull a) {
    return __uint_as_float((unsigned)a) + __uint_as_float((unsigned)(a >> 32));
}
__device__ __forceinline__ void cp16(uint32_t dst, const void* src) {
    asm volatile("cp.async.cg.shared.global [%0], [%1], 16;" :: "r"(dst), "l"(src) : "memory");
}
__device__ __forceinline__ void mbar_wait(uint32_t addr) {
    asm volatile(
        "{\n\t"
        ".reg .pred P;\n\t"
        "LAB_%=:\n\t"
        "mbarrier.try_wait.parity.acquire.cta.shared::cta.b64 P, [%0], 0, 0x989680;\n\t"
        "@!P bra LAB_%=;\n\t"
        "}\n\t"
        :: "r"(addr) : "memory");
}

__global__ __launch_bounds__(TPB) void cf_kernel(
    const int*   __restrict__ user,     // [B]
    const int*   __restrict__ items,    // [B,SB]
    const float* __restrict__ ufac,     // [N_USERS, PP, FF]
    const float* __restrict__ ifac,     // [N_ITEMS, FF]
    float*       __restrict__ pred,     // [B,SB]
    float*       __restrict__ scores,   // [B,SB,PP]
    int B)
{
    extern __shared__ __align__(16) char smem[];
    __shared__ ull mbar[RPB];

    const int tid = threadIdx.x;
    const long long b0 = (long long)blockIdx.x * RPB;

    const uint32_t sv = (uint32_t)__cvta_generic_to_shared(smem);
    const uint32_t su = sv + U_OFF;
    const uint32_t mb = (uint32_t)__cvta_generic_to_shared(mbar);

    if (tid == 0) {
        #pragma unroll
        for (int i = 0; i < RPB; i++)
            asm volatile("mbarrier.init.shared.b64 [%0], %1;" :: "r"(mb + 8u * i), "r"(TPB) : "memory");
    }
    __syncthreads();

    // ---- Async gather, one mbarrier per batch ----
    #pragma unroll
    for (int bb = 0; bb < RPB; bb++) {
        long long bcl = b0 + bb; if (bcl >= B) bcl = B - 1;
        const int* idxp = items + bcl * SB;
        const float* ubp = ufac + (long long)__ldg(&user[bcl]) * (PP * FF);

        // v: 200 rows x 256B = 3200 x 16B ops, coalesced per row (16 consecutive lanes/row)
        for (int i = tid; i < SB * 16; i += TPB) {
            const int r = i >> 4;
            const int c = i & 15;
            const int idx = __ldg(idxp + r);
            cp16(sv + (uint32_t)((bb * SB + r) * VPITCH + c * 16),
                 ifac + (long long)idx * FF + (c << 2));
        }
        // u: 2048B = 128 x 16B ops
        if (tid < 128) cp16(su + (uint32_t)(bb * U_SZ + tid * 16), ubp + tid * 4);

        // deferred arrive: fires when this thread's copies (batches <= bb) complete
        asm volatile("cp.async.mbarrier.arrive.noinc.shared::cta.b64 [%0];" :: "r"(mb + 8u * bb) : "memory");
    }

    // ---- Compute: thread t<200 -> batch t/50, rows s0+{0,50,100,150} ----
    if (tid < NCOMP) {
        const int bb  = tid / 50;
        const int sb0 = tid - bb * 50;
        const long long b = b0 + bb;
        if (b < B) {
            mbar_wait(mb + 8u * bb);   // wait ONLY this batch's tile (overlaps later gathers)

            const uint32_t ub = su + bb * U_SZ;
            uint32_t va[RR];
            #pragma unroll
            for (int h = 0; h < RR; h++)
                va[h] = sv + (uint32_t)((bb * SB + sb0 + 50 * h) * VPITCH);

            ull acc[RR][PP];
            #pragma unroll
            for (int h = 0; h < RR; h++)
                #pragma unroll
                for (int p = 0; p < PP; p++) acc[h][p] = 0ull;

            #pragma unroll
            for (int cc = 0; cc < FF / 4; cc++) {
                ull vx[RR], vy[RR];
                #pragma unroll
                for (int h = 0; h < RR; h++) lds16(vx[h], vy[h], va[h] + cc * 16);
                #pragma unroll
                for (int p = 0; p < PP; p++) {
                    ull ux, uy;
                    lds16(ux, uy, ub + p * 256 + cc * 16);   // broadcast
                    #pragma unroll
                    for (int h = 0; h < RR; h++) {
                        acc[h][p] = fma2(vx[h], ux, acc[h][p]);
                        acc[h][p] = fma2(vy[h], uy, acc[h][p]);
                    }
                }
            }

            // softmax over 8 personas; pred = sum_p a_p * r_p
            #pragma unroll
            for (int h = 0; h < RR; h++) {
                float r[PP];
                #pragma unroll
                for (int p = 0; p < PP; p++) r[p] = hsum2(acc[h][p]);

                float m = r[0];
                #pragma unroll
                for (int p = 1; p < PP; p++) m = fmaxf(m, r[p]);
                float e[PP], sum = 0.f;
                #pragma unroll
                for (int p = 0; p < PP; p++) { e[p] = __expf(r[p] - m); sum += e[p]; }
                const float inv = 1.f / sum;

                float a[PP], pr = 0.f;
                #pragma unroll
                for (int p = 0; p < PP; p++) { a[p] = e[p] * inv; pr = fmaf(a[p], r[p], pr); }

                const int s = sb0 + 50 * h;
                const long long g = b * SB + s;
                pred[g] = pr;
                float4* so = (float4*)(scores + g * (long long)PP);
                so[0] = make_float4(a[0], a[1], a[2], a[3]);
                so[1] = make_float4(a[4], a[5], a[6], a[7]);
            }
        }
    }
}

extern "C" void kernel_launch(void* const* d_in, const int* in_sizes, int n_in,
                              void* d_out, int out_size) {
    const int*   user  = (const int*)d_in[0];
    const int*   items = (const int*)d_in[1];
    const float* ufac  = (const float*)d_in[2];
    const float* ifac  = (const float*)d_in[3];

    const int B = in_sizes[0];

    float* out    = (float*)d_out;
    float* pred   = out;                        // [B,SB]
    float* scores = out + (long long)B * SB;    // [B,SB,PP]

    cudaFuncSetAttribute(cf_kernel, cudaFuncAttributeMaxDynamicSharedMemorySize, SMEMB);

    const int grid = (B + RPB - 1) / RPB;
    cf_kernel<<<grid, TPB, SMEMB>>>(user, items, ufac, ifac, pred, scores, B);
}

// round 6
// speedup vs baseline: 1.6889x; 1.6889x over previous
#include <cuda_runtime.h>
#include <cstdint>

#define PP     8       // personas
#define FF     64      // factor dim
#define SB     200     // items per batch row
#define RPB    2       // batches per CTA
#define TPB    256
#define VPITCH 272     // 17 x 16B: odd pitch -> conflict-free LDS.128
#define U_SZ   (PP * FF * 4)            // 2048 B per user
#define U_OFF  (RPB * SB * VPITCH)      // 108800
#define SMEMB  (U_OFF + RPB * U_SZ)     // 112896 B -> 2 CTAs/SM

typedef unsigned long long ull;

__device__ __forceinline__ ull fma2(ull a, ull b, ull c) {
    ull d; asm("fma.rn.f32x2 %0, %1, %2, %3;" : "=l"(d) : "l"(a), "l"(b), "l"(c)); return d;
}
__device__ __forceinline__ void lds16(ull& a, ull& b, uint32_t addr) {
    asm volatile("ld.shared.v2.b64 {%0,%1}, [%2];" : "=l"(a), "=l"(b) : "r"(addr));
}
__device__ __forceinline__ float hsum2(ull a) {
    return __uint_as_float((unsigned)a) + __uint_as_float((unsigned)(a >> 32));
}
__device__ __forceinline__ void cp16(uint32_t dst, const void* src) {
    asm volatile("cp.async.cg.shared.global [%0], [%1], 16;" :: "r"(dst), "l"(src) : "memory");
}
__device__ __forceinline__ void mbar_wait(uint32_t addr) {
    asm volatile(
        "{\n\t"
        ".reg .pred P;\n\t"
        "LAB_%=:\n\t"
        "mbarrier.try_wait.parity.acquire.cta.shared::cta.b64 P, [%0], 0, 0x989680;\n\t"
        "@!P bra LAB_%=;\n\t"
        "}\n\t"
        :: "r"(addr) : "memory");
}

__global__ __launch_bounds__(TPB, 2) void cf_kernel(
    const int*   __restrict__ user,     // [B]
    const int*   __restrict__ items,    // [B,SB]
    const float* __restrict__ ufac,     // [N_USERS, PP, FF]
    const float* __restrict__ ifac,     // [N_ITEMS, FF]
    float*       __restrict__ pred,     // [B,SB]
    float*       __restrict__ scores,   // [B,SB,PP]
    int B)
{
    extern __shared__ __align__(16) char smem[];
    __shared__ ull mbar[RPB];

    const int tid = threadIdx.x;
    const long long b0 = (long long)blockIdx.x * RPB;

    const uint32_t sv = (uint32_t)__cvta_generic_to_shared(smem);
    const uint32_t su = sv + U_OFF;
    const uint32_t mb = (uint32_t)__cvta_generic_to_shared(mbar);

    if (tid == 0) {
        #pragma unroll
        for (int i = 0; i < RPB; i++)
            asm volatile("mbarrier.init.shared.b64 [%0], %1;" :: "r"(mb + 8u * i), "r"(TPB) : "memory");
    }
    __syncthreads();

    // ---- Async gather: coalesced cp.async, one mbarrier per batch ----
    #pragma unroll
    for (int bb = 0; bb < RPB; bb++) {
        long long bcl = b0 + bb; if (bcl >= B) bcl = B - 1;
        const int* idxp = items + bcl * SB;
        const float* ubp = ufac + (long long)__ldg(&user[bcl]) * (PP * FF);

        // v: 200 rows x 16 chunks of 16B (16 consecutive lanes cover a row)
        for (int i = tid; i < SB * 16; i += TPB) {
            const int r = i >> 4;
            const int c = i & 15;
            const int idx = __ldg(idxp + r);
            cp16(sv + (uint32_t)((bb * SB + r) * VPITCH + c * 16),
                 ifac + (long long)idx * FF + (c << 2));
        }
        // u: 128 x 16B
        if (tid < 128) cp16(su + (uint32_t)(bb * U_SZ + tid * 16), ubp + tid * 4);

        // fires when this thread's cp.asyncs issued so far (batches <= bb) complete
        asm volatile("cp.async.mbarrier.arrive.noinc.shared::cta.b64 [%0];" :: "r"(mb + 8u * bb) : "memory");
    }

    // ---- Compute: thread t<200 -> batch t/100, rows (s0, s0+100) ----
    if (tid < RPB * 100) {
        const int bb = tid / 100;
        const int s0 = tid - bb * 100;
        const long long b = b0 + bb;
        if (b < B) {
            mbar_wait(mb + 8u * bb);   // only this batch's tile

            const uint32_t ub  = su + bb * U_SZ;
            const uint32_t v0a = sv + (uint32_t)((bb * SB + s0)       * VPITCH);
            const uint32_t v1a = sv + (uint32_t)((bb * SB + s0 + 100) * VPITCH);

            ull acc0[PP], acc1[PP];
            #pragma unroll
            for (int p = 0; p < PP; p++) { acc0[p] = 0ull; acc1[p] = 0ull; }

            #pragma unroll
            for (int cc = 0; cc < FF / 4; cc++) {
                ull v0x, v0y, v1x, v1y;
                lds16(v0x, v0y, v0a + cc * 16);
                lds16(v1x, v1y, v1a + cc * 16);
                #pragma unroll
                for (int p = 0; p < PP; p++) {
                    ull ux, uy;
                    lds16(ux, uy, ub + p * 256 + cc * 16);   // broadcast
                    acc0[p] = fma2(v0x, ux, acc0[p]);
                    acc0[p] = fma2(v0y, uy, acc0[p]);
                    acc1[p] = fma2(v1x, ux, acc1[p]);
                    acc1[p] = fma2(v1y, uy, acc1[p]);
                }
            }

            // softmax over 8 personas; pred = sum_p a_p * r_p
            #pragma unroll 2
            for (int h = 0; h < 2; h++) {
                const ull* accp = (h == 0) ? acc0 : acc1;
                float r[PP];
                #pragma unroll
                for (int p = 0; p < PP; p++) r[p] = hsum2(accp[p]);

                float m = r[0];
                #pragma unroll
                for (int p = 1; p < PP; p++) m = fmaxf(m, r[p]);
                float e[PP], sum = 0.f;
                #pragma unroll
                for (int p = 0; p < PP; p++) { e[p] = __expf(r[p] - m); sum += e[p]; }
                const float inv = 1.f / sum;

                float a[PP], pr = 0.f;
                #pragma unroll
                for (int p = 0; p < PP; p++) { a[p] = e[p] * inv; pr = fmaf(a[p], r[p], pr); }

                const int s = s0 + 100 * h;
                const long long g = b * SB + s;
                pred[g] = pr;
                float4* so = (float4*)(scores + g * (long long)PP);
                so[0] = make_float4(a[0], a[1], a[2], a[3]);
                so[1] = make_float4(a[4], a[5], a[6], a[7]);
            }
        }
    }
}

extern "C" void kernel_launch(void* const* d_in, const int* in_sizes, int n_in,
                              void* d_out, int out_size) {
    const int*   user  = (const int*)d_in[0];
    const int*   items = (const int*)d_in[1];
    const float* ufac  = (const float*)d_in[2];
    const float* ifac  = (const float*)d_in[3];

    const int B = in_sizes[0];

    float* out    = (float*)d_out;
    float* pred   = out;                        // [B,SB]
    float* scores = out + (long long)B * SB;    // [B,SB,PP]

    cudaFuncSetAttribute(cf_kernel, cudaFuncAttributeMaxDynamicSharedMemorySize, SMEMB);

    const int grid = (B + RPB - 1) / RPB;
    cf_kernel<<<grid, TPB, SMEMB>>>(user, items, ufac, ifac, pred, scores, B);
}

// round 7
// speedup vs baseline: 1.8490x; 1.0948x over previous
#include <cuda_runtime.h>
#include <cstdint>

#define PP     8       // personas
#define FF     64      // factor dim
#define SB     200     // items per batch row
#define TPB    256
#define VPITCH 272     // 17 x 16B: odd pitch -> conflict-free LDS.128
#define U_OFF  (SB * VPITCH)        // 54400
#define SMEMB  (U_OFF + PP*FF*4)    // 56448 B -> 4 CTAs/SM

typedef unsigned long long ull;

__device__ __forceinline__ ull fma2(ull a, ull b, ull c) {
    ull d; asm("fma.rn.f32x2 %0, %1, %2, %3;" : "=l"(d) : "l"(a), "l"(b), "l"(c)); return d;
}
__device__ __forceinline__ void lds16(ull& a, ull& b, uint32_t addr) {
    asm volatile("ld.shared.v2.b64 {%0,%1}, [%2];" : "=l"(a), "=l"(b) : "r"(addr));
}
__device__ __forceinline__ float hsum2(ull a) {
    return __uint_as_float((unsigned)a) + __uint_as_float((unsigned)(a >> 32));
}
__device__ __forceinline__ void cp16(uint32_t dst, const void* src) {
    asm volatile("cp.async.cg.shared.global [%0], [%1], 16;" :: "r"(dst), "l"(src) : "memory");
}
__device__ __forceinline__ void mbar_wait(uint32_t addr) {
    asm volatile(
        "{\n\t"
        ".reg .pred P;\n\t"
        "LAB_%=:\n\t"
        "mbarrier.try_wait.parity.acquire.cta.shared::cta.b64 P, [%0], 0, 0x989680;\n\t"
        "@!P bra LAB_%=;\n\t"
        "}\n\t"
        :: "r"(addr) : "memory");
}

__global__ __launch_bounds__(TPB, 4) void cf_kernel(
    const int*   __restrict__ user,     // [B]
    const int*   __restrict__ items,    // [B,SB]
    const float* __restrict__ ufac,     // [N_USERS, PP, FF]
    const float* __restrict__ ifac,     // [N_ITEMS, FF]
    float*       __restrict__ pred,     // [B,SB]
    float*       __restrict__ scores)   // [B,SB,PP]
{
    extern __shared__ __align__(16) char smem[];
    __shared__ ull mbar;

    const int tid = threadIdx.x;
    const long long b = blockIdx.x;

    const uint32_t sv = (uint32_t)__cvta_generic_to_shared(smem);
    const uint32_t su = sv + U_OFF;
    const uint32_t mb = (uint32_t)__cvta_generic_to_shared(&mbar);

    if (tid == 0)
        asm volatile("mbarrier.init.shared.b64 [%0], %1;" :: "r"(mb), "r"(TPB) : "memory");
    __syncthreads();

    // ---- Async gather: v = 200 rows x 16 chunks of 16B, coalesced; u = 128 x 16B ----
    const int* idxp = items + b * SB;
    const float* ubp = ufac + (long long)__ldg(&user[b]) * (PP * FF);
    #pragma unroll
    for (int k = 0; k < 13; k++) {
        const int i = tid + k * TPB;
        if (i < SB * 16) {
            const int r = i >> 4;
            const int c = i & 15;
            const int idx = __ldg(idxp + r);
            cp16(sv + (uint32_t)(r * VPITCH + c * 16),
                 ifac + (long long)idx * FF + (c << 2));
        }
    }
    if (tid < 128) cp16(su + (uint32_t)(tid * 16), ubp + tid * 4);
    asm volatile("cp.async.mbarrier.arrive.noinc.shared::cta.b64 [%0];" :: "r"(mb) : "memory");

    // ---- Compute: pair threads (2k, 2k+1) share rows (k, k+100); each does 4 personas ----
    if (tid < 2 * (SB / 2)) {        // 200 compute threads
        mbar_wait(mb);

        const int pair = tid >> 1;   // 0..99
        const int half = tid & 1;    // persona half
        const uint32_t v0a = sv + (uint32_t)(pair * VPITCH);
        const uint32_t v1a = v0a + 100u * VPITCH;
        const uint32_t ua  = su + (uint32_t)(half * 4 * 256);

        ull acc0[4], acc1[4];
        #pragma unroll
        for (int p = 0; p < 4; p++) { acc0[p] = 0ull; acc1[p] = 0ull; }

        #pragma unroll
        for (int cc = 0; cc < FF / 4; cc++) {
            ull v0x, v0y, v1x, v1y;
            lds16(v0x, v0y, v0a + cc * 16);   // adjacent lanes same addr -> broadcast merge
            lds16(v1x, v1y, v1a + cc * 16);
            #pragma unroll
            for (int p = 0; p < 4; p++) {
                ull ux, uy;
                lds16(ux, uy, ua + p * 256 + cc * 16);   // broadcast (2 addrs/warp)
                acc0[p] = fma2(v0x, ux, acc0[p]);
                acc0[p] = fma2(v0y, uy, acc0[p]);
                acc1[p] = fma2(v1x, ux, acc1[p]);
                acc1[p] = fma2(v1y, uy, acc1[p]);
            }
        }

        // own 4 persona scores per row; exchange with partner lane for the other 4
        float mine[2][4];
        #pragma unroll
        for (int p = 0; p < 4; p++) { mine[0][p] = hsum2(acc0[p]); mine[1][p] = hsum2(acc1[p]); }

        const unsigned msk = __activemask();
        float oth[2][4];
        #pragma unroll
        for (int j = 0; j < 2; j++)
            #pragma unroll
            for (int p = 0; p < 4; p++)
                oth[j][p] = __shfl_xor_sync(msk, mine[j][p], 1);

        #pragma unroll
        for (int j = 0; j < 2; j++) {
            float r[PP];
            #pragma unroll
            for (int p = 0; p < 4; p++) {
                r[half * 4 + p]       = mine[j][p];
                r[(1 - half) * 4 + p] = oth[j][p];
            }

            float m = r[0];
            #pragma unroll
            for (int p = 1; p < PP; p++) m = fmaxf(m, r[p]);
            float e[PP], sum = 0.f;
            #pragma unroll
            for (int p = 0; p < PP; p++) { e[p] = __expf(r[p] - m); sum += e[p]; }
            const float inv = 1.f / sum;

            float a[PP], pr = 0.f;
            #pragma unroll
            for (int p = 0; p < PP; p++) { a[p] = e[p] * inv; pr = fmaf(a[p], r[p], pr); }

            const int s = pair + 100 * j;
            const long long g = b * SB + s;
            if (half == 0) pred[g] = pr;
            // each thread writes its own persona-half (coalesced float4)
            *(float4*)(scores + g * (long long)PP + half * 4) =
                make_float4(a[half * 4], a[half * 4 + 1], a[half * 4 + 2], a[half * 4 + 3]);
        }
    }
}

extern "C" void kernel_launch(void* const* d_in, const int* in_sizes, int n_in,
                              void* d_out, int out_size) {
    const int*   user  = (const int*)d_in[0];
    const int*   items = (const int*)d_in[1];
    const float* ufac  = (const float*)d_in[2];
    const float* ifac  = (const float*)d_in[3];

    const int B = in_sizes[0];

    float* out    = (float*)d_out;
    float* pred   = out;                        // [B,SB]
    float* scores = out + (long long)B * SB;    // [B,SB,PP]

    cudaFuncSetAttribute(cf_kernel, cudaFuncAttributeMaxDynamicSharedMemorySize, SMEMB);

    cf_kernel<<<B, TPB, SMEMB>>>(user, items, ufac, ifac, pred, scores);
}